// round 14
// baseline (speedup 1.0000x reference)
#include <cuda_runtime.h>
#include <cuda_bf16.h>
#include <math.h>
#include <cstdint>

#define Bsz  128
#define Tlen 1024
#define Hd   256
#define NOUT 2

typedef unsigned long long u64;

// Scratch buffers (device globals — allocation is forbidden)
__device__ float         g_bufA[Bsz * Tlen * Hd];   // pre-activations (fp32)
__device__ __nv_bfloat16 g_xhi[Bsz * Tlen * Hd];    // x hi
__device__ __nv_bfloat16 g_xlo[Bsz * Tlen * Hd];    // x lo
__device__ __nv_bfloat16 g_h1hi[Bsz * Tlen * Hd];   // h1 hi
__device__ __nv_bfloat16 g_h1lo[Bsz * Tlen * Hd];   // h1 lo
__device__ __nv_bfloat16 g_w0hi[Hd * Hd], g_w0lo[Hd * Hd];
__device__ __nv_bfloat16 g_w1hi[Hd * Hd], g_w1lo[Hd * Hd];

// ---------- packed fp32x2 helpers ----------
__device__ __forceinline__ void fma2(u64& acc, u64 a, u64 b) {
    asm("fma.rn.f32x2 %0, %1, %2, %0;" : "+l"(acc) : "l"(a), "l"(b));
}
__device__ __forceinline__ u64 add2(u64 a, u64 b) {
    u64 r; asm("add.rn.f32x2 %0, %1, %2;" : "=l"(r) : "l"(a), "l"(b)); return r;
}
__device__ __forceinline__ float2 unpk(u64 v) {
    float2 r; asm("mov.b64 {%0, %1}, %2;" : "=f"(r.x), "=f"(r.y) : "l"(v)); return r;
}
__device__ __forceinline__ uint32_t smem_to_u32(const void* p) {
    uint32_t a;
    asm("{ .reg .u64 t; cvta.to.shared.u64 t, %1; cvt.u32.u64 %0, t; }"
        : "=r"(a) : "l"(p));
    return a;
}

// ---------- HMMA helpers ----------
#define LDSM_X4(r0, r1, r2, r3, addr)                                         \
    asm volatile("ldmatrix.sync.aligned.m8n8.x4.shared.b16 {%0,%1,%2,%3}, [%4];" \
                 : "=r"(r0), "=r"(r1), "=r"(r2), "=r"(r3) : "r"(addr))

#define MMA16816(d, a, b0, b1)                                                \
    asm volatile("mma.sync.aligned.m16n8k16.row.col.f32.bf16.bf16.f32 "       \
                 "{%0,%1,%2,%3}, {%4,%5,%6,%7}, {%8,%9}, {%0,%1,%2,%3};"      \
                 : "+f"((d)[0]), "+f"((d)[1]), "+f"((d)[2]), "+f"((d)[3])     \
                 : "r"((a)[0]), "r"((a)[1]), "r"((a)[2]), "r"((a)[3]),        \
                   "r"(b0), "r"(b1))

// =============================================================================
// fp32 -> bf16 hi/lo conversion prepass (vectorized by 4)
// =============================================================================
__global__ void conv_hilo_kernel(const float* __restrict__ src,
                                 __nv_bfloat16* __restrict__ hi,
                                 __nv_bfloat16* __restrict__ lo, int n4)
{
    int i = blockIdx.x * blockDim.x + threadIdx.x;
    if (i >= n4) return;
    float4 v = ((const float4*)src)[i];
    __nv_bfloat162 h01 = __floats2bfloat162_rn(v.x, v.y);
    __nv_bfloat162 h23 = __floats2bfloat162_rn(v.z, v.w);
    float2 f01 = __bfloat1622float2(h01);
    float2 f23 = __bfloat1622float2(h23);
    __nv_bfloat162 l01 = __floats2bfloat162_rn(v.x - f01.x, v.y - f01.y);
    __nv_bfloat162 l23 = __floats2bfloat162_rn(v.z - f23.x, v.w - f23.y);
    uint32_t uh01, uh23, ul01, ul23;
    memcpy(&uh01, &h01, 4); memcpy(&uh23, &h23, 4);
    memcpy(&ul01, &l01, 4); memcpy(&ul23, &l23, 4);
    ((uint2*)hi)[i] = make_uint2(uh01, uh23);
    ((uint2*)lo)[i] = make_uint2(ul01, ul23);
}

// =============================================================================
// HMMA GEMM (copy-staged, R13-verbatim): out[m][n] = sum_k A[m][k]*W[n][k]+bias
// =============================================================================
#define GH_STRIDE 144
#define GH_TILE   (128 * GH_STRIDE)
#define GH_SMEM   (4 * GH_TILE)

__global__ void __launch_bounds__(256, 2) gemm_hmma_kernel(
    const __nv_bfloat16* __restrict__ Ahi, const __nv_bfloat16* __restrict__ Alo,
    const __nv_bfloat16* __restrict__ Bhi, const __nv_bfloat16* __restrict__ Blo,
    const float* __restrict__ bias, float* __restrict__ out)
{
    extern __shared__ char smem[];
    char* pAhi = smem;
    char* pAlo = smem + GH_TILE;
    char* pBhi = smem + 2 * GH_TILE;
    char* pBlo = smem + 3 * GH_TILE;
    const uint32_t sAhi = smem_to_u32(pAhi);
    const uint32_t sAlo = sAhi + GH_TILE;
    const uint32_t sBhi = sAhi + 2 * GH_TILE;
    const uint32_t sBlo = sAhi + 3 * GH_TILE;

    const int t    = threadIdx.x;
    const int lane = t & 31;
    const int wid  = t >> 5;
    const int nt   = blockIdx.x & 1;
    const int mt   = blockIdx.x >> 1;
    const int m0   = mt * 128, n0 = nt * 128;
    const int wm   = (wid & 3) * 32;
    const int wn   = (wid >> 2) * 64;

    float acc[2][8][4];
    #pragma unroll
    for (int f = 0; f < 2; ++f)
        #pragma unroll
        for (int n8 = 0; n8 < 8; ++n8)
            #pragma unroll
            for (int e = 0; e < 4; ++e) acc[f][n8][e] = 0.f;

    const __nv_bfloat16* Abh = Ahi + (size_t)m0 * Hd;
    const __nv_bfloat16* Abl = Alo + (size_t)m0 * Hd;
    const __nv_bfloat16* Wbh = Bhi + (size_t)n0 * Hd;
    const __nv_bfloat16* Wbl = Blo + (size_t)n0 * Hd;

    const uint32_t aRowOff = (uint32_t)(lane & 15) * GH_STRIDE +
                             (uint32_t)(lane >> 4) * 16;
    const uint32_t bRowOff = ((uint32_t)((lane >> 4) << 3) + (lane & 7)) * GH_STRIDE +
                             (uint32_t)((lane >> 3) & 1) * 16;

    for (int chunk = 0; chunk < 4; ++chunk) {
        __syncthreads();
        const int kq4 = chunk << 3;
        #pragma unroll
        for (int i = 0; i < 4; ++i) {
            int idx = t + (i << 8);
            int row = idx >> 3, q = idx & 7;
            uint32_t off = (uint32_t)row * GH_STRIDE + (uint32_t)q * 16;
            *(uint4*)(pAhi + off) = ((const uint4*)(Abh + row * Hd))[kq4 + q];
            *(uint4*)(pAlo + off) = ((const uint4*)(Abl + row * Hd))[kq4 + q];
        }
        #pragma unroll
        for (int i = 0; i < 4; ++i) {
            int idx = t + (i << 8);
            int row = idx >> 3, q = idx & 7;
            uint32_t off = (uint32_t)row * GH_STRIDE + (uint32_t)q * 16;
            *(uint4*)(pBhi + off) = ((const uint4*)(Wbh + row * Hd))[kq4 + q];
            *(uint4*)(pBlo + off) = ((const uint4*)(Wbl + row * Hd))[kq4 + q];
        }
        __syncthreads();

        #pragma unroll
        for (int pass = 0; pass < 3; ++pass) {
            const uint32_t ab = (pass == 2) ? sAlo : sAhi;
            const uint32_t bb = (pass == 1) ? sBlo : sBhi;
            const uint32_t aaddr = ab + (uint32_t)wm * GH_STRIDE + aRowOff;
            const uint32_t baddr = bb + (uint32_t)wn * GH_STRIDE + bRowOff;
            #pragma unroll
            for (int ks = 0; ks < 4; ++ks) {
                uint32_t a0[4], a1[4];
                LDSM_X4(a0[0], a0[1], a0[2], a0[3], aaddr + ks * 32);
                LDSM_X4(a1[0], a1[1], a1[2], a1[3],
                        aaddr + 16 * GH_STRIDE + ks * 32);
                #pragma unroll
                for (int p = 0; p < 4; ++p) {
                    uint32_t b[4];
                    LDSM_X4(b[0], b[1], b[2], b[3],
                            baddr + p * 16 * GH_STRIDE + ks * 32);
                    MMA16816(acc[0][p * 2 + 0], a0, b[0], b[1]);
                    MMA16816(acc[0][p * 2 + 1], a0, b[2], b[3]);
                    MMA16816(acc[1][p * 2 + 0], a1, b[0], b[1]);
                    MMA16816(acc[1][p * 2 + 1], a1, b[2], b[3]);
                }
            }
        }
    }

    const int r  = lane >> 2;
    const int c2 = (lane & 3) * 2;
    #pragma unroll
    for (int f = 0; f < 2; ++f) {
        #pragma unroll
        for (int n8 = 0; n8 < 8; ++n8) {
            int n = n0 + wn + n8 * 8 + c2;
            float2 bv = *(const float2*)&bias[n];
            int m = m0 + wm + f * 16 + r;
            float2 r0; r0.x = acc[f][n8][0] + bv.x; r0.y = acc[f][n8][1] + bv.y;
            float2 r1; r1.x = acc[f][n8][2] + bv.x; r1.y = acc[f][n8][3] + bv.y;
            *(float2*)&out[(size_t)m * Hd + n] = r0;
            *(float2*)&out[(size_t)(m + 8) * Hd + n] = r1;
        }
    }
}

// =============================================================================
// Recurrence v8: 1 CTA = TWO batch rows, 64 CTAs, 512 threads.
// Thread t -> output j = t>>1, K-half kh = t&1 (pair reduce via shfl_xor,
// one barrier per step). Each thread applies its weights to BOTH batches'
// h vectors (weight traffic unchanged, fixed costs amortized 2x).
// Weights/thread = 128 floats: 72 in registers + 56 in smem.
// =============================================================================
#define RREG 18   // ulonglong2 in registers (72 floats)
#define RSM  14   // ulonglong2 in smem (56 floats)
#define HSTR 132
#define HBAT (2 * HSTR)          // 264 floats per batch per parity
#define HPAR (2 * HBAT)          // 528 floats per parity (2 batches)
#define HBUF (2 * HPAR)          // 1056 floats total
#define REC_SMEM (HBUF * 4 + RSM * 512 * 16)

__device__ __forceinline__ float fast_tanh(float x) {
    float e = __expf(2.0f * x);
    return 1.0f - 2.0f * __fdividef(1.0f, e + 1.0f);
}

template<bool WRITE_H, bool FINAL>
__global__ void __launch_bounds__(512, 1) recur_kernel(
    const float* __restrict__ pre, const float* __restrict__ Whh,
    __nv_bfloat16* __restrict__ houthi, __nv_bfloat16* __restrict__ houtlo,
    const float* __restrict__ fcw, const float* __restrict__ fcb,
    float* __restrict__ out)
{
    extern __shared__ float smf[];
    float* hbuf = smf;                                   // [2 par][2 bat][264]
    ulonglong2* Wsm = (ulonglong2*)(smf + HBUF);         // [RSM][512]

    const int t  = threadIdx.x;
    const int b0 = blockIdx.x * 2;       // first batch of the pair
    const int j  = t >> 1;
    const int kh = t & 1;

    const ulonglong2* wg =
        (const ulonglong2*)(Whh + (size_t)j * Hd + (kh << 7));
    ulonglong2 wr[RREG];
    #pragma unroll
    for (int c = 0; c < RREG; ++c) wr[c] = wg[c];
    #pragma unroll
    for (int c = 0; c < RSM; ++c) Wsm[c * 512 + t] = wg[RREG + c];

    for (int i = t; i < HBUF; i += 512) hbuf[i] = 0.f;

    const float* preb0 = pre + (size_t)b0 * Tlen * Hd;
    const float* preb1 = preb0 + (size_t)Tlen * Hd;
    float p0 = preb0[j];
    float p1 = preb1[j];
    const int wslot = j + ((j >> 7) << 2);
    __syncthreads();

    for (int step = 0; step < Tlen; ++step) {
        int sn = (step + 1 < Tlen) ? step + 1 : step;
        float pn0 = preb0[sn * Hd + j];
        float pn1 = preb1[sn * Hd + j];

        const float* hb = hbuf + (step & 1) * HPAR + kh * HSTR;
        const ulonglong2* h20 = (const ulonglong2*)hb;           // batch 0
        const ulonglong2* h21 = (const ulonglong2*)(hb + HBAT);  // batch 1

        u64 x0 = 0ull, x1 = 0ull, x2 = 0ull, x3 = 0ull;
        u64 y0 = 0ull, y1 = 0ull, y2 = 0ull, y3 = 0ull;

        // smem-resident weights first (fills LSU early); reuse wv both batches
        #pragma unroll
        for (int c = 0; c < RSM; ++c) {
            ulonglong2 wv = Wsm[c * 512 + t];
            ulonglong2 hv0 = h20[RREG + c];
            ulonglong2 hv1 = h21[RREG + c];
            fma2(x0, wv.x, hv0.x);
            fma2(x1, wv.y, hv0.y);
            fma2(y0, wv.x, hv1.x);
            fma2(y1, wv.y, hv1.y);
        }
        #pragma unroll
        for (int c = 0; c < RREG; ++c) {
            ulonglong2 hv0 = h20[c];
            ulonglong2 hv1 = h21[c];
            fma2(x2, wr[c].x, hv0.x);
            fma2(x3, wr[c].y, hv0.y);
            fma2(y2, wr[c].x, hv1.x);
            fma2(y3, wr[c].y, hv1.y);
        }

        float2 f0 = unpk(add2(add2(x0, x1), add2(x2, x3)));
        float2 f1 = unpk(add2(add2(y0, y1), add2(y2, y3)));
        float d0 = f0.x + f0.y;
        float d1 = f1.x + f1.y;
        d0 += __shfl_xor_sync(0xffffffffu, d0, 1);
        d1 += __shfl_xor_sync(0xffffffffu, d1, 1);

        float hn0 = fast_tanh(p0 + d0);
        float hn1 = fast_tanh(p1 + d1);

        if (kh == 0) {
            float* nb = hbuf + ((step + 1) & 1) * HPAR;
            nb[wslot]        = hn0;
            nb[HBAT + wslot] = hn1;
            if (WRITE_H) {
                __nv_bfloat16 hh0 = __float2bfloat16_rn(hn0);
                __nv_bfloat16 hh1 = __float2bfloat16_rn(hn1);
                size_t o0 = ((size_t)b0 * Tlen + step) * Hd + j;
                size_t o1 = o0 + (size_t)Tlen * Hd;
                houthi[o0] = hh0;
                houtlo[o0] = __float2bfloat16_rn(hn0 - __bfloat162float(hh0));
                houthi[o1] = hh1;
                houtlo[o1] = __float2bfloat16_rn(hn1 - __bfloat162float(hh1));
            }
        }
        __syncthreads();
        p0 = pn0;
        p1 = pn1;
    }

    if (FINAL) {
        // final h in parity 0 (Tlen even); one warp per (batch, output)
        if (t < 128) {
            int bt   = t >> 6;          // 0 or 1
            int o    = (t >> 5) & 1;    // output 0 or 1
            int lane = t & 31;
            const float* hb = hbuf + bt * HBAT;
            float s = 0.f;
            #pragma unroll
            for (int q = 0; q < 8; ++q) {
                int jj = lane + (q << 5);
                s += hb[jj + ((jj >> 7) << 2)] * fcw[o * Hd + jj];
            }
            #pragma unroll
            for (int off = 16; off; off >>= 1)
                s += __shfl_down_sync(0xffffffffu, s, off);
            if (lane == 0) out[(b0 + bt) * NOUT + o] = s + fcb[o];
        }
    }
}

extern "C" void kernel_launch(void* const* d_in, const int* in_sizes, int n_in,
                              void* d_out, int out_size) {
    const float* x    = (const float*)d_in[0];
    const float* Wxh0 = (const float*)d_in[1];
    const float* Whh0 = (const float*)d_in[2];
    const float* b0   = (const float*)d_in[3];
    const float* Wxh1 = (const float*)d_in[4];
    const float* Whh1 = (const float*)d_in[5];
    const float* b1   = (const float*)d_in[6];
    const float* fcw  = (const float*)d_in[7];
    const float* fcb  = (const float*)d_in[8];
    float* out = (float*)d_out;

    float* bufA = nullptr;
    __nv_bfloat16 *xhi, *xlo, *h1hi, *h1lo, *w0hi, *w0lo, *w1hi, *w1lo;
    cudaGetSymbolAddress((void**)&bufA, g_bufA);
    cudaGetSymbolAddress((void**)&xhi, g_xhi);
    cudaGetSymbolAddress((void**)&xlo, g_xlo);
    cudaGetSymbolAddress((void**)&h1hi, g_h1hi);
    cudaGetSymbolAddress((void**)&h1lo, g_h1lo);
    cudaGetSymbolAddress((void**)&w0hi, g_w0hi);
    cudaGetSymbolAddress((void**)&w0lo, g_w0lo);
    cudaGetSymbolAddress((void**)&w1hi, g_w1hi);
    cudaGetSymbolAddress((void**)&w1lo, g_w1lo);

    cudaFuncSetAttribute(gemm_hmma_kernel,
        cudaFuncAttributeMaxDynamicSharedMemorySize, GH_SMEM);
    cudaFuncSetAttribute(recur_kernel<true, false>,
        cudaFuncAttributeMaxDynamicSharedMemorySize, REC_SMEM);
    cudaFuncSetAttribute(recur_kernel<false, true>,
        cudaFuncAttributeMaxDynamicSharedMemorySize, REC_SMEM);

    const int NX4 = (Bsz * Tlen * Hd) / 4;
    const int NW4 = (Hd * Hd) / 4;

    conv_hilo_kernel<<<NX4 / 256, 256>>>(x, xhi, xlo, NX4);
    conv_hilo_kernel<<<NW4 / 256, 256>>>(Wxh0, w0hi, w0lo, NW4);
    conv_hilo_kernel<<<NW4 / 256, 256>>>(Wxh1, w1hi, w1lo, NW4);

    // Layer 1
    gemm_hmma_kernel<<<2048, 256, GH_SMEM>>>(xhi, xlo, w0hi, w0lo, b0, bufA);
    recur_kernel<true, false><<<Bsz / 2, 512, REC_SMEM>>>(
        bufA, Whh0, h1hi, h1lo, nullptr, nullptr, nullptr);

    // Layer 2 + head
    gemm_hmma_kernel<<<2048, 256, GH_SMEM>>>(h1hi, h1lo, w1hi, w1lo, b1, bufA);
    recur_kernel<false, true><<<Bsz / 2, 512, REC_SMEM>>>(
        bufA, Whh1, nullptr, nullptr, fcw, fcb, out);
}

// round 15
// speedup vs baseline: 1.4797x; 1.4797x over previous
#include <cuda_runtime.h>
#include <cuda_bf16.h>
#include <math.h>
#include <cstdint>

#define Bsz  128
#define Tlen 1024
#define Hd   256
#define NOUT 2

typedef unsigned long long u64;

// Scratch buffers (device globals — allocation is forbidden)
__device__ float         g_bufA[Bsz * Tlen * Hd];   // pre-activations (fp32)
__device__ __nv_bfloat16 g_xhi[Bsz * Tlen * Hd];    // x hi
__device__ __nv_bfloat16 g_xlo[Bsz * Tlen * Hd];    // x lo
__device__ __nv_bfloat16 g_h1hi[Bsz * Tlen * Hd];   // h1 hi
__device__ __nv_bfloat16 g_h1lo[Bsz * Tlen * Hd];   // h1 lo
__device__ __nv_bfloat16 g_w0hi[Hd * Hd], g_w0lo[Hd * Hd];
__device__ __nv_bfloat16 g_w1hi[Hd * Hd], g_w1lo[Hd * Hd];

// ---------- packed fp32x2 helpers ----------
__device__ __forceinline__ void fma2(u64& acc, u64 a, u64 b) {
    asm("fma.rn.f32x2 %0, %1, %2, %0;" : "+l"(acc) : "l"(a), "l"(b));
}
__device__ __forceinline__ u64 add2(u64 a, u64 b) {
    u64 r; asm("add.rn.f32x2 %0, %1, %2;" : "=l"(r) : "l"(a), "l"(b)); return r;
}
__device__ __forceinline__ float2 unpk(u64 v) {
    float2 r; asm("mov.b64 {%0, %1}, %2;" : "=f"(r.x), "=f"(r.y) : "l"(v)); return r;
}
__device__ __forceinline__ uint32_t smem_to_u32(const void* p) {
    uint32_t a;
    asm("{ .reg .u64 t; cvta.to.shared.u64 t, %1; cvt.u32.u64 %0, t; }"
        : "=r"(a) : "l"(p));
    return a;
}

// ---------- HMMA / cp.async helpers ----------
#define LDSM_X4(r0, r1, r2, r3, addr)                                         \
    asm volatile("ldmatrix.sync.aligned.m8n8.x4.shared.b16 {%0,%1,%2,%3}, [%4];" \
                 : "=r"(r0), "=r"(r1), "=r"(r2), "=r"(r3) : "r"(addr))

#define MMA16816(d, a, b0, b1)                                                \
    asm volatile("mma.sync.aligned.m16n8k16.row.col.f32.bf16.bf16.f32 "       \
                 "{%0,%1,%2,%3}, {%4,%5,%6,%7}, {%8,%9}, {%0,%1,%2,%3};"      \
                 : "+f"((d)[0]), "+f"((d)[1]), "+f"((d)[2]), "+f"((d)[3])     \
                 : "r"((a)[0]), "r"((a)[1]), "r"((a)[2]), "r"((a)[3]),        \
                   "r"(b0), "r"(b1))

#define CP_ASYNC16(saddr, gptr)                                               \
    asm volatile("cp.async.cg.shared.global [%0], [%1], 16;"                  \
                 :: "r"(saddr), "l"(gptr))
#define CP_COMMIT() asm volatile("cp.async.commit_group;" ::: "memory")
#define CP_WAIT(n)  asm volatile("cp.async.wait_group %0;" :: "n"(n) : "memory")

// =============================================================================
// fp32 -> bf16 hi/lo conversion prepass (vectorized by 4)
// =============================================================================
__global__ void conv_hilo_kernel(const float* __restrict__ src,
                                 __nv_bfloat16* __restrict__ hi,
                                 __nv_bfloat16* __restrict__ lo, int n4)
{
    int i = blockIdx.x * blockDim.x + threadIdx.x;
    if (i >= n4) return;
    float4 v = ((const float4*)src)[i];
    __nv_bfloat162 h01 = __floats2bfloat162_rn(v.x, v.y);
    __nv_bfloat162 h23 = __floats2bfloat162_rn(v.z, v.w);
    float2 f01 = __bfloat1622float2(h01);
    float2 f23 = __bfloat1622float2(h23);
    __nv_bfloat162 l01 = __floats2bfloat162_rn(v.x - f01.x, v.y - f01.y);
    __nv_bfloat162 l23 = __floats2bfloat162_rn(v.z - f23.x, v.w - f23.y);
    uint32_t uh01, uh23, ul01, ul23;
    memcpy(&uh01, &h01, 4); memcpy(&uh23, &h23, 4);
    memcpy(&ul01, &l01, 4); memcpy(&ul23, &l23, 4);
    ((uint2*)hi)[i] = make_uint2(uh01, uh23);
    ((uint2*)lo)[i] = make_uint2(ul01, ul23);
}

// =============================================================================
// HMMA GEMM, cp.async double-buffered: out[m][n] = sum_k A[m][k]*W[n][k]+bias
// Tile 128m x 128n; 8 warps of 32m x 64n. bf16 hi/lo, 3 passes, fp32 acc.
// K in 4 chunks of 64; chunk c+1 prefetched via cp.async while c computes.
// =============================================================================
#define GH_STRIDE 144                    // bytes per 64-k row (72 bf16)
#define GH_TILE   (128 * GH_STRIDE)      // 18432 B per tile buffer
#define GH_CHUNK  (4 * GH_TILE)          // Ahi/Alo/Bhi/Blo for one chunk
#define GH_SMEM   (2 * GH_CHUNK)         // double-buffered: 147456 B

__global__ void __launch_bounds__(256, 1) gemm_hmma_kernel(
    const __nv_bfloat16* __restrict__ Ahi, const __nv_bfloat16* __restrict__ Alo,
    const __nv_bfloat16* __restrict__ Bhi, const __nv_bfloat16* __restrict__ Blo,
    const float* __restrict__ bias, float* __restrict__ out)
{
    extern __shared__ char smem[];
    const uint32_t sbase = smem_to_u32(smem);

    const int t    = threadIdx.x;
    const int lane = t & 31;
    const int wid  = t >> 5;
    const int nt   = blockIdx.x & 1;
    const int mt   = blockIdx.x >> 1;
    const int m0   = mt * 128, n0 = nt * 128;
    const int wm   = (wid & 3) * 32;
    const int wn   = (wid >> 2) * 64;

    float acc[2][8][4];
    #pragma unroll
    for (int f = 0; f < 2; ++f)
        #pragma unroll
        for (int n8 = 0; n8 < 8; ++n8)
            #pragma unroll
            for (int e = 0; e < 4; ++e) acc[f][n8][e] = 0.f;

    const __nv_bfloat16* Abh = Ahi + (size_t)m0 * Hd;
    const __nv_bfloat16* Abl = Alo + (size_t)m0 * Hd;
    const __nv_bfloat16* Wbh = Bhi + (size_t)n0 * Hd;
    const __nv_bfloat16* Wbl = Blo + (size_t)n0 * Hd;

    // this thread's staging slots: 4 (row,q) pairs covering 128 rows x 8 uint4
    const int srow0 = t >> 3;        // rows srow0 + 32*i
    const int sq    = t & 7;         // uint4 column within 64-k row

    const uint32_t aRowOff = (uint32_t)(lane & 15) * GH_STRIDE +
                             (uint32_t)(lane >> 4) * 16;
    const uint32_t bRowOff = ((uint32_t)((lane >> 4) << 3) + (lane & 7)) * GH_STRIDE +
                             (uint32_t)((lane >> 3) & 1) * 16;

    // stage chunk `c` into buffer `buf` via cp.async (one commit group)
    auto stage = [&](int c, int buf) {
        const int kq4 = c << 3;
        const uint32_t base = sbase + buf * GH_CHUNK;
        #pragma unroll
        for (int i = 0; i < 4; ++i) {
            int row = srow0 + (i << 5);
            uint32_t off = (uint32_t)row * GH_STRIDE + (uint32_t)sq * 16;
            const uint4* ga_h = (const uint4*)(Abh + row * Hd) + kq4 + sq;
            const uint4* ga_l = (const uint4*)(Abl + row * Hd) + kq4 + sq;
            const uint4* gb_h = (const uint4*)(Wbh + row * Hd) + kq4 + sq;
            const uint4* gb_l = (const uint4*)(Wbl + row * Hd) + kq4 + sq;
            CP_ASYNC16(base + off, ga_h);
            CP_ASYNC16(base + GH_TILE + off, ga_l);
            CP_ASYNC16(base + 2 * GH_TILE + off, gb_h);
            CP_ASYNC16(base + 3 * GH_TILE + off, gb_l);
        }
        CP_COMMIT();
    };

    stage(0, 0);

    for (int c = 0; c < 4; ++c) {
        if (c < 3) stage(c + 1, (c + 1) & 1);
        if (c < 3) { CP_WAIT(1); } else { CP_WAIT(0); }
        __syncthreads();

        const uint32_t cb = sbase + (c & 1) * GH_CHUNK;
        #pragma unroll
        for (int pass = 0; pass < 3; ++pass) {
            const uint32_t ab = cb + ((pass == 2) ? GH_TILE : 0u);
            const uint32_t bb = cb + 2 * GH_TILE + ((pass == 1) ? GH_TILE : 0u);
            const uint32_t aaddr = ab + (uint32_t)wm * GH_STRIDE + aRowOff;
            const uint32_t baddr = bb + (uint32_t)wn * GH_STRIDE + bRowOff;
            #pragma unroll
            for (int ks = 0; ks < 4; ++ks) {
                uint32_t a0[4], a1[4];
                LDSM_X4(a0[0], a0[1], a0[2], a0[3], aaddr + ks * 32);
                LDSM_X4(a1[0], a1[1], a1[2], a1[3],
                        aaddr + 16 * GH_STRIDE + ks * 32);
                #pragma unroll
                for (int p = 0; p < 4; ++p) {
                    uint32_t b[4];
                    LDSM_X4(b[0], b[1], b[2], b[3],
                            baddr + p * 16 * GH_STRIDE + ks * 32);
                    MMA16816(acc[0][p * 2 + 0], a0, b[0], b[1]);
                    MMA16816(acc[0][p * 2 + 1], a0, b[2], b[3]);
                    MMA16816(acc[1][p * 2 + 0], a1, b[0], b[1]);
                    MMA16816(acc[1][p * 2 + 1], a1, b[2], b[3]);
                }
            }
        }
        __syncthreads();   // all ldsm done before next stage overwrites buffer
    }

    const int r  = lane >> 2;
    const int c2 = (lane & 3) * 2;
    #pragma unroll
    for (int f = 0; f < 2; ++f) {
        #pragma unroll
        for (int n8 = 0; n8 < 8; ++n8) {
            int n = n0 + wn + n8 * 8 + c2;
            float2 bv = *(const float2*)&bias[n];
            int m = m0 + wm + f * 16 + r;
            float2 r0; r0.x = acc[f][n8][0] + bv.x; r0.y = acc[f][n8][1] + bv.y;
            float2 r1; r1.x = acc[f][n8][2] + bv.x; r1.y = acc[f][n8][3] + bv.y;
            *(float2*)&out[(size_t)m * Hd + n] = r0;
            *(float2*)&out[(size_t)(m + 8) * Hd + n] = r1;
        }
    }
}

// =============================================================================
// Recurrence (R13 exact — 1.063ms, design optimum): 1 CTA = 1 batch row,
// 512 threads, pair-split j=t>>1/kh=t&1, shfl_xor reduce, one barrier,
// 80/48 weight split. WRITE_H emits h as bf16 hi/lo for the next GEMM.
// =============================================================================
#define RREG 20
#define RSM  12
#define HSTR 132
#define HBUF (2 * 2 * HSTR)
#define REC_SMEM (HBUF * 4 + RSM * 512 * 16)

__device__ __forceinline__ float fast_tanh(float x) {
    float e = __expf(2.0f * x);
    return 1.0f - 2.0f * __fdividef(1.0f, e + 1.0f);
}

template<bool WRITE_H, bool FINAL>
__global__ void __launch_bounds__(512, 1) recur_kernel(
    const float* __restrict__ pre, const float* __restrict__ Whh,
    __nv_bfloat16* __restrict__ houthi, __nv_bfloat16* __restrict__ houtlo,
    const float* __restrict__ fcw, const float* __restrict__ fcb,
    float* __restrict__ out)
{
    extern __shared__ float smf[];
    float* hbuf = smf;                                   // [2][2*HSTR]
    ulonglong2* Wsm = (ulonglong2*)(smf + HBUF);         // [RSM][512]

    const int t  = threadIdx.x;
    const int b  = blockIdx.x;
    const int j  = t >> 1;
    const int kh = t & 1;

    const ulonglong2* wg =
        (const ulonglong2*)(Whh + (size_t)j * Hd + (kh << 7));
    ulonglong2 wr[RREG];
    #pragma unroll
    for (int c = 0; c < RREG; ++c) wr[c] = wg[c];
    #pragma unroll
    for (int c = 0; c < RSM; ++c) Wsm[c * 512 + t] = wg[RREG + c];

    if (t < HBUF) hbuf[t] = 0.f;

    const float* preb = pre + (size_t)b * Tlen * Hd;
    float p = preb[j];
    const int wslot = j + ((j >> 7) << 2);
    __syncthreads();

    for (int step = 0; step < Tlen; ++step) {
        int sn = (step + 1 < Tlen) ? step + 1 : step;
        float pn = preb[sn * Hd + j];

        const ulonglong2* h2 =
            (const ulonglong2*)(hbuf + (step & 1) * (2 * HSTR) + kh * HSTR);

        u64 a0 = 0ull, a1 = 0ull, a2 = 0ull, a3 = 0ull, a4 = 0ull, a5 = 0ull;

        #pragma unroll
        for (int c = 0; c < RSM; ++c) {
            ulonglong2 hv = h2[RREG + c];
            ulonglong2 wv = Wsm[c * 512 + t];
            fma2(a4, wv.x, hv.x);
            fma2(a5, wv.y, hv.y);
        }
        #pragma unroll
        for (int c = 0; c < RREG; c += 2) {
            ulonglong2 hv = h2[c];
            fma2(a0, wr[c].x, hv.x);
            fma2(a1, wr[c].y, hv.y);
            ulonglong2 hw = h2[c + 1];
            fma2(a2, wr[c + 1].x, hw.x);
            fma2(a3, wr[c + 1].y, hw.y);
        }

        u64 s01 = add2(add2(add2(a0, a1), add2(a2, a3)), add2(a4, a5));
        float2 f = unpk(s01);
        float d = f.x + f.y;
        d += __shfl_xor_sync(0xffffffffu, d, 1);

        float hn = fast_tanh(p + d);

        if (kh == 0) {
            hbuf[((step + 1) & 1) * (2 * HSTR) + wslot] = hn;
            if (WRITE_H) {
                __nv_bfloat16 hh = __float2bfloat16_rn(hn);
                float rem = hn - __bfloat162float(hh);
                size_t o = ((size_t)b * Tlen + step) * Hd + j;
                houthi[o] = hh;
                houtlo[o] = __float2bfloat16_rn(rem);
            }
        }
        __syncthreads();
        p = pn;
    }

    if (FINAL) {
        if (t < 64) {
            int o = t >> 5, lane = t & 31;
            float s = 0.f;
            #pragma unroll
            for (int q = 0; q < 8; ++q) {
                int jj = lane + (q << 5);
                s += hbuf[jj + ((jj >> 7) << 2)] * fcw[o * Hd + jj];
            }
            #pragma unroll
            for (int off = 16; off; off >>= 1)
                s += __shfl_down_sync(0xffffffffu, s, off);
            if (lane == 0) out[b * NOUT + o] = s + fcb[o];
        }
    }
}

extern "C" void kernel_launch(void* const* d_in, const int* in_sizes, int n_in,
                              void* d_out, int out_size) {
    const float* x    = (const float*)d_in[0];
    const float* Wxh0 = (const float*)d_in[1];
    const float* Whh0 = (const float*)d_in[2];
    const float* b0   = (const float*)d_in[3];
    const float* Wxh1 = (const float*)d_in[4];
    const float* Whh1 = (const float*)d_in[5];
    const float* b1   = (const float*)d_in[6];
    const float* fcw  = (const float*)d_in[7];
    const float* fcb  = (const float*)d_in[8];
    float* out = (float*)d_out;

    float* bufA = nullptr;
    __nv_bfloat16 *xhi, *xlo, *h1hi, *h1lo, *w0hi, *w0lo, *w1hi, *w1lo;
    cudaGetSymbolAddress((void**)&bufA, g_bufA);
    cudaGetSymbolAddress((void**)&xhi, g_xhi);
    cudaGetSymbolAddress((void**)&xlo, g_xlo);
    cudaGetSymbolAddress((void**)&h1hi, g_h1hi);
    cudaGetSymbolAddress((void**)&h1lo, g_h1lo);
    cudaGetSymbolAddress((void**)&w0hi, g_w0hi);
    cudaGetSymbolAddress((void**)&w0lo, g_w0lo);
    cudaGetSymbolAddress((void**)&w1hi, g_w1hi);
    cudaGetSymbolAddress((void**)&w1lo, g_w1lo);

    cudaFuncSetAttribute(gemm_hmma_kernel,
        cudaFuncAttributeMaxDynamicSharedMemorySize, GH_SMEM);
    cudaFuncSetAttribute(recur_kernel<true, false>,
        cudaFuncAttributeMaxDynamicSharedMemorySize, REC_SMEM);
    cudaFuncSetAttribute(recur_kernel<false, true>,
        cudaFuncAttributeMaxDynamicSharedMemorySize, REC_SMEM);

    const int NX4 = (Bsz * Tlen * Hd) / 4;
    const int NW4 = (Hd * Hd) / 4;

    conv_hilo_kernel<<<NX4 / 256, 256>>>(x, xhi, xlo, NX4);
    conv_hilo_kernel<<<NW4 / 256, 256>>>(Wxh0, w0hi, w0lo, NW4);
    conv_hilo_kernel<<<NW4 / 256, 256>>>(Wxh1, w1hi, w1lo, NW4);

    // Layer 1
    gemm_hmma_kernel<<<2048, 256, GH_SMEM>>>(xhi, xlo, w0hi, w0lo, b0, bufA);
    recur_kernel<true, false><<<Bsz, 512, REC_SMEM>>>(
        bufA, Whh0, h1hi, h1lo, nullptr, nullptr, nullptr);

    // Layer 2 + head
    gemm_hmma_kernel<<<2048, 256, GH_SMEM>>>(h1hi, h1lo, w1hi, w1lo, b1, bufA);
    recur_kernel<false, true><<<Bsz, 512, REC_SMEM>>>(
        bufA, Whh1, nullptr, nullptr, fcw, fcb, out);
}

// round 16
// speedup vs baseline: 1.4880x; 1.0056x over previous
#include <cuda_runtime.h>
#include <cuda_bf16.h>
#include <math.h>
#include <cstdint>

#define Bsz  128
#define Tlen 1024
#define Hd   256
#define NOUT 2

typedef unsigned long long u64;

// Scratch buffers (device globals — allocation is forbidden)
__device__ float         g_bufA[Bsz * Tlen * Hd];   // pre-activations (fp32)
__device__ __nv_bfloat16 g_xhi[Bsz * Tlen * Hd];    // x hi
__device__ __nv_bfloat16 g_xlo[Bsz * Tlen * Hd];    // x lo
__device__ __nv_bfloat16 g_h1hi[Bsz * Tlen * Hd];   // h1 hi
__device__ __nv_bfloat16 g_h1lo[Bsz * Tlen * Hd];   // h1 lo
__device__ __nv_bfloat16 g_w0hi[Hd * Hd], g_w0lo[Hd * Hd];
__device__ __nv_bfloat16 g_w1hi[Hd * Hd], g_w1lo[Hd * Hd];

// ---------- packed fp32x2 helpers ----------
__device__ __forceinline__ void fma2(u64& acc, u64 a, u64 b) {
    asm("fma.rn.f32x2 %0, %1, %2, %0;" : "+l"(acc) : "l"(a), "l"(b));
}
__device__ __forceinline__ u64 add2(u64 a, u64 b) {
    u64 r; asm("add.rn.f32x2 %0, %1, %2;" : "=l"(r) : "l"(a), "l"(b)); return r;
}
__device__ __forceinline__ float2 unpk(u64 v) {
    float2 r; asm("mov.b64 {%0, %1}, %2;" : "=f"(r.x), "=f"(r.y) : "l"(v)); return r;
}
__device__ __forceinline__ uint32_t smem_to_u32(const void* p) {
    uint32_t a;
    asm("{ .reg .u64 t; cvta.to.shared.u64 t, %1; cvt.u32.u64 %0, t; }"
        : "=r"(a) : "l"(p));
    return a;
}

// ---------- HMMA / cp.async helpers ----------
#define LDSM_X4(r0, r1, r2, r3, addr)                                         \
    asm volatile("ldmatrix.sync.aligned.m8n8.x4.shared.b16 {%0,%1,%2,%3}, [%4];" \
                 : "=r"(r0), "=r"(r1), "=r"(r2), "=r"(r3) : "r"(addr))

#define MMA16816(d, a, b0, b1)                                                \
    asm volatile("mma.sync.aligned.m16n8k16.row.col.f32.bf16.bf16.f32 "       \
                 "{%0,%1,%2,%3}, {%4,%5,%6,%7}, {%8,%9}, {%0,%1,%2,%3};"      \
                 : "+f"((d)[0]), "+f"((d)[1]), "+f"((d)[2]), "+f"((d)[3])     \
                 : "r"((a)[0]), "r"((a)[1]), "r"((a)[2]), "r"((a)[3]),        \
                   "r"(b0), "r"(b1))

#define CP_ASYNC16(saddr, gptr)                                               \
    asm volatile("cp.async.cg.shared.global [%0], [%1], 16;"                  \
                 :: "r"(saddr), "l"(gptr))
#define CP_COMMIT() asm volatile("cp.async.commit_group;" ::: "memory")
#define CP_WAIT(n)  asm volatile("cp.async.wait_group %0;" :: "n"(n) : "memory")

// =============================================================================
// fp32 -> bf16 hi/lo conversion prepass (vectorized by 4)
// =============================================================================
__global__ void conv_hilo_kernel(const float* __restrict__ src,
                                 __nv_bfloat16* __restrict__ hi,
                                 __nv_bfloat16* __restrict__ lo, int n4)
{
    int i = blockIdx.x * blockDim.x + threadIdx.x;
    if (i >= n4) return;
    float4 v = ((const float4*)src)[i];
    __nv_bfloat162 h01 = __floats2bfloat162_rn(v.x, v.y);
    __nv_bfloat162 h23 = __floats2bfloat162_rn(v.z, v.w);
    float2 f01 = __bfloat1622float2(h01);
    float2 f23 = __bfloat1622float2(h23);
    __nv_bfloat162 l01 = __floats2bfloat162_rn(v.x - f01.x, v.y - f01.y);
    __nv_bfloat162 l23 = __floats2bfloat162_rn(v.z - f23.x, v.w - f23.y);
    uint32_t uh01, uh23, ul01, ul23;
    memcpy(&uh01, &h01, 4); memcpy(&uh23, &h23, 4);
    memcpy(&ul01, &l01, 4); memcpy(&ul23, &l23, 4);
    ((uint2*)hi)[i] = make_uint2(uh01, uh23);
    ((uint2*)lo)[i] = make_uint2(ul01, ul23);
}

// =============================================================================
// HMMA GEMM, cp.async double-buffered, fragment-hoisted inner loop:
// out[m][n] = sum_k A[m][k]*W[n][k] + bias[n]
// Tile 128m x 128n; 8 warps of 32m x 64n. bf16 hi/lo, fp32 acc.
// Per k16-step: load Ahi/Alo/Bhi/Blo fragments ONCE (12 ldsm), issue all
// 48 MMAs (hh + hl + lh) from registers.
// =============================================================================
#define GH_STRIDE 144                    // bytes per 64-k row (72 bf16)
#define GH_TILE   (128 * GH_STRIDE)      // 18432 B per tile buffer
#define GH_CHUNK  (4 * GH_TILE)          // Ahi/Alo/Bhi/Blo for one chunk
#define GH_SMEM   (2 * GH_CHUNK)         // double-buffered: 147456 B

__global__ void __launch_bounds__(256, 1) gemm_hmma_kernel(
    const __nv_bfloat16* __restrict__ Ahi, const __nv_bfloat16* __restrict__ Alo,
    const __nv_bfloat16* __restrict__ Bhi, const __nv_bfloat16* __restrict__ Blo,
    const float* __restrict__ bias, float* __restrict__ out)
{
    extern __shared__ char smem[];
    const uint32_t sbase = smem_to_u32(smem);

    const int t    = threadIdx.x;
    const int lane = t & 31;
    const int wid  = t >> 5;
    const int nt   = blockIdx.x & 1;
    const int mt   = blockIdx.x >> 1;
    const int m0   = mt * 128, n0 = nt * 128;
    const int wm   = (wid & 3) * 32;
    const int wn   = (wid >> 2) * 64;

    float acc[2][8][4];
    #pragma unroll
    for (int f = 0; f < 2; ++f)
        #pragma unroll
        for (int n8 = 0; n8 < 8; ++n8)
            #pragma unroll
            for (int e = 0; e < 4; ++e) acc[f][n8][e] = 0.f;

    const __nv_bfloat16* Abh = Ahi + (size_t)m0 * Hd;
    const __nv_bfloat16* Abl = Alo + (size_t)m0 * Hd;
    const __nv_bfloat16* Wbh = Bhi + (size_t)n0 * Hd;
    const __nv_bfloat16* Wbl = Blo + (size_t)n0 * Hd;

    const int srow0 = t >> 3;        // staging rows srow0 + 32*i
    const int sq    = t & 7;         // uint4 column within 64-k row

    const uint32_t aRowOff = (uint32_t)(lane & 15) * GH_STRIDE +
                             (uint32_t)(lane >> 4) * 16;
    const uint32_t bRowOff = ((uint32_t)((lane >> 4) << 3) + (lane & 7)) * GH_STRIDE +
                             (uint32_t)((lane >> 3) & 1) * 16;

    auto stage = [&](int c, int buf) {
        const int kq4 = c << 3;
        const uint32_t base = sbase + buf * GH_CHUNK;
        #pragma unroll
        for (int i = 0; i < 4; ++i) {
            int row = srow0 + (i << 5);
            uint32_t off = (uint32_t)row * GH_STRIDE + (uint32_t)sq * 16;
            const uint4* ga_h = (const uint4*)(Abh + row * Hd) + kq4 + sq;
            const uint4* ga_l = (const uint4*)(Abl + row * Hd) + kq4 + sq;
            const uint4* gb_h = (const uint4*)(Wbh + row * Hd) + kq4 + sq;
            const uint4* gb_l = (const uint4*)(Wbl + row * Hd) + kq4 + sq;
            CP_ASYNC16(base + off, ga_h);
            CP_ASYNC16(base + GH_TILE + off, ga_l);
            CP_ASYNC16(base + 2 * GH_TILE + off, gb_h);
            CP_ASYNC16(base + 3 * GH_TILE + off, gb_l);
        }
        CP_COMMIT();
    };

    stage(0, 0);

    for (int c = 0; c < 4; ++c) {
        if (c < 3) stage(c + 1, (c + 1) & 1);
        if (c < 3) { CP_WAIT(1); } else { CP_WAIT(0); }
        __syncthreads();

        const uint32_t cb = sbase + (c & 1) * GH_CHUNK;
        const uint32_t aHi = cb + (uint32_t)wm * GH_STRIDE + aRowOff;
        const uint32_t aLo = aHi + GH_TILE;
        const uint32_t bHi = cb + 2 * GH_TILE + (uint32_t)wn * GH_STRIDE + bRowOff;
        const uint32_t bLo = bHi + GH_TILE;

        #pragma unroll
        for (int ks = 0; ks < 4; ++ks) {
            const uint32_t ko = (uint32_t)ks * 32;
            // A fragments (hi + lo), both 16-row halves
            uint32_t a0h[4], a1h[4], a0l[4], a1l[4];
            LDSM_X4(a0h[0], a0h[1], a0h[2], a0h[3], aHi + ko);
            LDSM_X4(a1h[0], a1h[1], a1h[2], a1h[3], aHi + 16 * GH_STRIDE + ko);
            LDSM_X4(a0l[0], a0l[1], a0l[2], a0l[3], aLo + ko);
            LDSM_X4(a1l[0], a1l[1], a1l[2], a1l[3], aLo + 16 * GH_STRIDE + ko);
            #pragma unroll
            for (int p = 0; p < 4; ++p) {
                uint32_t bh[4], bl[4];
                LDSM_X4(bh[0], bh[1], bh[2], bh[3],
                        bHi + p * 16 * GH_STRIDE + ko);
                LDSM_X4(bl[0], bl[1], bl[2], bl[3],
                        bLo + p * 16 * GH_STRIDE + ko);
                // hi*hi
                MMA16816(acc[0][p * 2 + 0], a0h, bh[0], bh[1]);
                MMA16816(acc[0][p * 2 + 1], a0h, bh[2], bh[3]);
                MMA16816(acc[1][p * 2 + 0], a1h, bh[0], bh[1]);
                MMA16816(acc[1][p * 2 + 1], a1h, bh[2], bh[3]);
                // hi*lo
                MMA16816(acc[0][p * 2 + 0], a0h, bl[0], bl[1]);
                MMA16816(acc[0][p * 2 + 1], a0h, bl[2], bl[3]);
                MMA16816(acc[1][p * 2 + 0], a1h, bl[0], bl[1]);
                MMA16816(acc[1][p * 2 + 1], a1h, bl[2], bl[3]);
                // lo*hi
                MMA16816(acc[0][p * 2 + 0], a0l, bh[0], bh[1]);
                MMA16816(acc[0][p * 2 + 1], a0l, bh[2], bh[3]);
                MMA16816(acc[1][p * 2 + 0], a1l, bh[0], bh[1]);
                MMA16816(acc[1][p * 2 + 1], a1l, bh[2], bh[3]);
            }
        }
        __syncthreads();   // all ldsm done before next stage overwrites buffer
    }

    const int r  = lane >> 2;
    const int c2 = (lane & 3) * 2;
    #pragma unroll
    for (int f = 0; f < 2; ++f) {
        #pragma unroll
        for (int n8 = 0; n8 < 8; ++n8) {
            int n = n0 + wn + n8 * 8 + c2;
            float2 bv = *(const float2*)&bias[n];
            int m = m0 + wm + f * 16 + r;
            float2 r0; r0.x = acc[f][n8][0] + bv.x; r0.y = acc[f][n8][1] + bv.y;
            float2 r1; r1.x = acc[f][n8][2] + bv.x; r1.y = acc[f][n8][3] + bv.y;
            *(float2*)&out[(size_t)m * Hd + n] = r0;
            *(float2*)&out[(size_t)(m + 8) * Hd + n] = r1;
        }
    }
}

// =============================================================================
// Recurrence (R13 exact — 1.063ms, design optimum): 1 CTA = 1 batch row,
// 512 threads, pair-split j=t>>1/kh=t&1, shfl_xor reduce, one barrier,
// 80/48 weight split. WRITE_H emits h as bf16 hi/lo for the next GEMM.
// =============================================================================
#define RREG 20
#define RSM  12
#define HSTR 132
#define HBUF (2 * 2 * HSTR)
#define REC_SMEM (HBUF * 4 + RSM * 512 * 16)

__device__ __forceinline__ float fast_tanh(float x) {
    float e = __expf(2.0f * x);
    return 1.0f - 2.0f * __fdividef(1.0f, e + 1.0f);
}

template<bool WRITE_H, bool FINAL>
__global__ void __launch_bounds__(512, 1) recur_kernel(
    const float* __restrict__ pre, const float* __restrict__ Whh,
    __nv_bfloat16* __restrict__ houthi, __nv_bfloat16* __restrict__ houtlo,
    const float* __restrict__ fcw, const float* __restrict__ fcb,
    float* __restrict__ out)
{
    extern __shared__ float smf[];
    float* hbuf = smf;                                   // [2][2*HSTR]
    ulonglong2* Wsm = (ulonglong2*)(smf + HBUF);         // [RSM][512]

    const int t  = threadIdx.x;
    const int b  = blockIdx.x;
    const int j  = t >> 1;
    const int kh = t & 1;

    const ulonglong2* wg =
        (const ulonglong2*)(Whh + (size_t)j * Hd + (kh << 7));
    ulonglong2 wr[RREG];
    #pragma unroll
    for (int c = 0; c < RREG; ++c) wr[c] = wg[c];
    #pragma unroll
    for (int c = 0; c < RSM; ++c) Wsm[c * 512 + t] = wg[RREG + c];

    if (t < HBUF) hbuf[t] = 0.f;

    const float* preb = pre + (size_t)b * Tlen * Hd;
    float p = preb[j];
    const int wslot = j + ((j >> 7) << 2);
    __syncthreads();

    for (int step = 0; step < Tlen; ++step) {
        int sn = (step + 1 < Tlen) ? step + 1 : step;
        float pn = preb[sn * Hd + j];

        const ulonglong2* h2 =
            (const ulonglong2*)(hbuf + (step & 1) * (2 * HSTR) + kh * HSTR);

        u64 a0 = 0ull, a1 = 0ull, a2 = 0ull, a3 = 0ull, a4 = 0ull, a5 = 0ull;

        #pragma unroll
        for (int c = 0; c < RSM; ++c) {
            ulonglong2 hv = h2[RREG + c];
            ulonglong2 wv = Wsm[c * 512 + t];
            fma2(a4, wv.x, hv.x);
            fma2(a5, wv.y, hv.y);
        }
        #pragma unroll
        for (int c = 0; c < RREG; c += 2) {
            ulonglong2 hv = h2[c];
            fma2(a0, wr[c].x, hv.x);
            fma2(a1, wr[c].y, hv.y);
            ulonglong2 hw = h2[c + 1];
            fma2(a2, wr[c + 1].x, hw.x);
            fma2(a3, wr[c + 1].y, hw.y);
        }

        u64 s01 = add2(add2(add2(a0, a1), add2(a2, a3)), add2(a4, a5));
        float2 f = unpk(s01);
        float d = f.x + f.y;
        d += __shfl_xor_sync(0xffffffffu, d, 1);

        float hn = fast_tanh(p + d);

        if (kh == 0) {
            hbuf[((step + 1) & 1) * (2 * HSTR) + wslot] = hn;
            if (WRITE_H) {
                __nv_bfloat16 hh = __float2bfloat16_rn(hn);
                float rem = hn - __bfloat162float(hh);
                size_t o = ((size_t)b * Tlen + step) * Hd + j;
                houthi[o] = hh;
                houtlo[o] = __float2bfloat16_rn(rem);
            }
        }
        __syncthreads();
        p = pn;
    }

    if (FINAL) {
        if (t < 64) {
            int o = t >> 5, lane = t & 31;
            float s = 0.f;
            #pragma unroll
            for (int q = 0; q < 8; ++q) {
                int jj = lane + (q << 5);
                s += hbuf[jj + ((jj >> 7) << 2)] * fcw[o * Hd + jj];
            }
            #pragma unroll
            for (int off = 16; off; off >>= 1)
                s += __shfl_down_sync(0xffffffffu, s, off);
            if (lane == 0) out[b * NOUT + o] = s + fcb[o];
        }
    }
}

extern "C" void kernel_launch(void* const* d_in, const int* in_sizes, int n_in,
                              void* d_out, int out_size) {
    const float* x    = (const float*)d_in[0];
    const float* Wxh0 = (const float*)d_in[1];
    const float* Whh0 = (const float*)d_in[2];
    const float* b0   = (const float*)d_in[3];
    const float* Wxh1 = (const float*)d_in[4];
    const float* Whh1 = (const float*)d_in[5];
    const float* b1   = (const float*)d_in[6];
    const float* fcw  = (const float*)d_in[7];
    const float* fcb  = (const float*)d_in[8];
    float* out = (float*)d_out;

    float* bufA = nullptr;
    __nv_bfloat16 *xhi, *xlo, *h1hi, *h1lo, *w0hi, *w0lo, *w1hi, *w1lo;
    cudaGetSymbolAddress((void**)&bufA, g_bufA);
    cudaGetSymbolAddress((void**)&xhi, g_xhi);
    cudaGetSymbolAddress((void**)&xlo, g_xlo);
    cudaGetSymbolAddress((void**)&h1hi, g_h1hi);
    cudaGetSymbolAddress((void**)&h1lo, g_h1lo);
    cudaGetSymbolAddress((void**)&w0hi, g_w0hi);
    cudaGetSymbolAddress((void**)&w0lo, g_w0lo);
    cudaGetSymbolAddress((void**)&w1hi, g_w1hi);
    cudaGetSymbolAddress((void**)&w1lo, g_w1lo);

    cudaFuncSetAttribute(gemm_hmma_kernel,
        cudaFuncAttributeMaxDynamicSharedMemorySize, GH_SMEM);
    cudaFuncSetAttribute(recur_kernel<true, false>,
        cudaFuncAttributeMaxDynamicSharedMemorySize, REC_SMEM);
    cudaFuncSetAttribute(recur_kernel<false, true>,
        cudaFuncAttributeMaxDynamicSharedMemorySize, REC_SMEM);

    const int NX4 = (Bsz * Tlen * Hd) / 4;
    const int NW4 = (Hd * Hd) / 4;

    conv_hilo_kernel<<<NX4 / 256, 256>>>(x, xhi, xlo, NX4);
    conv_hilo_kernel<<<NW4 / 256, 256>>>(Wxh0, w0hi, w0lo, NW4);
    conv_hilo_kernel<<<NW4 / 256, 256>>>(Wxh1, w1hi, w1lo, NW4);

    // Layer 1
    gemm_hmma_kernel<<<2048, 256, GH_SMEM>>>(xhi, xlo, w0hi, w0lo, b0, bufA);
    recur_kernel<true, false><<<Bsz, 512, REC_SMEM>>>(
        bufA, Whh0, h1hi, h1lo, nullptr, nullptr, nullptr);

    // Layer 2 + head
    gemm_hmma_kernel<<<2048, 256, GH_SMEM>>>(h1hi, h1lo, w1hi, w1lo, b1, bufA);
    recur_kernel<false, true><<<Bsz, 512, REC_SMEM>>>(
        bufA, Whh1, nullptr, nullptr, fcw, fcb, out);
}

// round 17
// speedup vs baseline: 1.6769x; 1.1269x over previous
#include <cuda_runtime.h>
#include <cuda_bf16.h>
#include <math.h>
#include <cstdint>

#define Bsz  128
#define Tlen 1024
#define Hd   256
#define NOUT 2

typedef unsigned long long u64;

// Scratch buffers (device globals — allocation is forbidden)
__device__ float         g_bufA[Bsz * Tlen * Hd];   // pre-activations (fp32)
__device__ __nv_bfloat16 g_xhi[Bsz * Tlen * Hd];    // x hi
__device__ __nv_bfloat16 g_xlo[Bsz * Tlen * Hd];    // x lo
__device__ __nv_bfloat16 g_h1hi[Bsz * Tlen * Hd];   // h1 hi
__device__ __nv_bfloat16 g_h1lo[Bsz * Tlen * Hd];   // h1 lo
__device__ __nv_bfloat16 g_w0hi[Hd * Hd], g_w0lo[Hd * Hd];
__device__ __nv_bfloat16 g_w1hi[Hd * Hd], g_w1lo[Hd * Hd];

// ---------- packed fp32x2 helpers ----------
__device__ __forceinline__ void fma2(u64& acc, u64 a, u64 b) {
    asm("fma.rn.f32x2 %0, %1, %2, %0;" : "+l"(acc) : "l"(a), "l"(b));
}
__device__ __forceinline__ u64 add2(u64 a, u64 b) {
    u64 r; asm("add.rn.f32x2 %0, %1, %2;" : "=l"(r) : "l"(a), "l"(b)); return r;
}
__device__ __forceinline__ float2 unpk(u64 v) {
    float2 r; asm("mov.b64 {%0, %1}, %2;" : "=f"(r.x), "=f"(r.y) : "l"(v)); return r;
}
__device__ __forceinline__ u64 mk64(uint32_t lo, uint32_t hi) {
    u64 r; asm("mov.b64 %0, {%1, %2};" : "=l"(r) : "r"(lo), "r"(hi)); return r;
}
__device__ __forceinline__ uint32_t smem_to_u32(const void* p) {
    uint32_t a;
    asm("{ .reg .u64 t; cvta.to.shared.u64 t, %1; cvt.u32.u64 %0, t; }"
        : "=r"(a) : "l"(p));
    return a;
}

// ---------- HMMA / cp.async helpers ----------
#define LDSM_X4(r0, r1, r2, r3, addr)                                         \
    asm volatile("ldmatrix.sync.aligned.m8n8.x4.shared.b16 {%0,%1,%2,%3}, [%4];" \
                 : "=r"(r0), "=r"(r1), "=r"(r2), "=r"(r3) : "r"(addr))

#define MMA16816(d, a, b0, b1)                                                \
    asm volatile("mma.sync.aligned.m16n8k16.row.col.f32.bf16.bf16.f32 "       \
                 "{%0,%1,%2,%3}, {%4,%5,%6,%7}, {%8,%9}, {%0,%1,%2,%3};"      \
                 : "+f"((d)[0]), "+f"((d)[1]), "+f"((d)[2]), "+f"((d)[3])     \
                 : "r"((a)[0]), "r"((a)[1]), "r"((a)[2]), "r"((a)[3]),        \
                   "r"(b0), "r"(b1))

#define CP_ASYNC16(saddr, gptr)                                               \
    asm volatile("cp.async.cg.shared.global [%0], [%1], 16;"                  \
                 :: "r"(saddr), "l"(gptr))
#define CP_COMMIT() asm volatile("cp.async.commit_group;" ::: "memory")
#define CP_WAIT(n)  asm volatile("cp.async.wait_group %0;" :: "n"(n) : "memory")

// =============================================================================
// fp32 -> bf16 hi/lo conversion prepass (vectorized by 4)
// =============================================================================
__global__ void conv_hilo_kernel(const float* __restrict__ src,
                                 __nv_bfloat16* __restrict__ hi,
                                 __nv_bfloat16* __restrict__ lo, int n4)
{
    int i = blockIdx.x * blockDim.x + threadIdx.x;
    if (i >= n4) return;
    float4 v = ((const float4*)src)[i];
    __nv_bfloat162 h01 = __floats2bfloat162_rn(v.x, v.y);
    __nv_bfloat162 h23 = __floats2bfloat162_rn(v.z, v.w);
    float2 f01 = __bfloat1622float2(h01);
    float2 f23 = __bfloat1622float2(h23);
    __nv_bfloat162 l01 = __floats2bfloat162_rn(v.x - f01.x, v.y - f01.y);
    __nv_bfloat162 l23 = __floats2bfloat162_rn(v.z - f23.x, v.w - f23.y);
    uint32_t uh01, uh23, ul01, ul23;
    memcpy(&uh01, &h01, 4); memcpy(&uh23, &h23, 4);
    memcpy(&ul01, &l01, 4); memcpy(&ul23, &l23, 4);
    ((uint2*)hi)[i] = make_uint2(uh01, uh23);
    ((uint2*)lo)[i] = make_uint2(ul01, ul23);
}

// =============================================================================
// HMMA GEMM (R16-verbatim): cp.async double-buffered, fragment-hoisted.
// =============================================================================
#define GH_STRIDE 144
#define GH_TILE   (128 * GH_STRIDE)
#define GH_CHUNK  (4 * GH_TILE)
#define GH_SMEM   (2 * GH_CHUNK)

__global__ void __launch_bounds__(256, 1) gemm_hmma_kernel(
    const __nv_bfloat16* __restrict__ Ahi, const __nv_bfloat16* __restrict__ Alo,
    const __nv_bfloat16* __restrict__ Bhi, const __nv_bfloat16* __restrict__ Blo,
    const float* __restrict__ bias, float* __restrict__ out)
{
    extern __shared__ char smem[];
    const uint32_t sbase = smem_to_u32(smem);

    const int t    = threadIdx.x;
    const int lane = t & 31;
    const int wid  = t >> 5;
    const int nt   = blockIdx.x & 1;
    const int mt   = blockIdx.x >> 1;
    const int m0   = mt * 128, n0 = nt * 128;
    const int wm   = (wid & 3) * 32;
    const int wn   = (wid >> 2) * 64;

    float acc[2][8][4];
    #pragma unroll
    for (int f = 0; f < 2; ++f)
        #pragma unroll
        for (int n8 = 0; n8 < 8; ++n8)
            #pragma unroll
            for (int e = 0; e < 4; ++e) acc[f][n8][e] = 0.f;

    const __nv_bfloat16* Abh = Ahi + (size_t)m0 * Hd;
    const __nv_bfloat16* Abl = Alo + (size_t)m0 * Hd;
    const __nv_bfloat16* Wbh = Bhi + (size_t)n0 * Hd;
    const __nv_bfloat16* Wbl = Blo + (size_t)n0 * Hd;

    const int srow0 = t >> 3;
    const int sq    = t & 7;

    const uint32_t aRowOff = (uint32_t)(lane & 15) * GH_STRIDE +
                             (uint32_t)(lane >> 4) * 16;
    const uint32_t bRowOff = ((uint32_t)((lane >> 4) << 3) + (lane & 7)) * GH_STRIDE +
                             (uint32_t)((lane >> 3) & 1) * 16;

    auto stage = [&](int c, int buf) {
        const int kq4 = c << 3;
        const uint32_t base = sbase + buf * GH_CHUNK;
        #pragma unroll
        for (int i = 0; i < 4; ++i) {
            int row = srow0 + (i << 5);
            uint32_t off = (uint32_t)row * GH_STRIDE + (uint32_t)sq * 16;
            const uint4* ga_h = (const uint4*)(Abh + row * Hd) + kq4 + sq;
            const uint4* ga_l = (const uint4*)(Abl + row * Hd) + kq4 + sq;
            const uint4* gb_h = (const uint4*)(Wbh + row * Hd) + kq4 + sq;
            const uint4* gb_l = (const uint4*)(Wbl + row * Hd) + kq4 + sq;
            CP_ASYNC16(base + off, ga_h);
            CP_ASYNC16(base + GH_TILE + off, ga_l);
            CP_ASYNC16(base + 2 * GH_TILE + off, gb_h);
            CP_ASYNC16(base + 3 * GH_TILE + off, gb_l);
        }
        CP_COMMIT();
    };

    stage(0, 0);

    for (int c = 0; c < 4; ++c) {
        if (c < 3) stage(c + 1, (c + 1) & 1);
        if (c < 3) { CP_WAIT(1); } else { CP_WAIT(0); }
        __syncthreads();

        const uint32_t cb = sbase + (c & 1) * GH_CHUNK;
        const uint32_t aHi = cb + (uint32_t)wm * GH_STRIDE + aRowOff;
        const uint32_t aLo = aHi + GH_TILE;
        const uint32_t bHi = cb + 2 * GH_TILE + (uint32_t)wn * GH_STRIDE + bRowOff;
        const uint32_t bLo = bHi + GH_TILE;

        #pragma unroll
        for (int ks = 0; ks < 4; ++ks) {
            const uint32_t ko = (uint32_t)ks * 32;
            uint32_t a0h[4], a1h[4], a0l[4], a1l[4];
            LDSM_X4(a0h[0], a0h[1], a0h[2], a0h[3], aHi + ko);
            LDSM_X4(a1h[0], a1h[1], a1h[2], a1h[3], aHi + 16 * GH_STRIDE + ko);
            LDSM_X4(a0l[0], a0l[1], a0l[2], a0l[3], aLo + ko);
            LDSM_X4(a1l[0], a1l[1], a1l[2], a1l[3], aLo + 16 * GH_STRIDE + ko);
            #pragma unroll
            for (int p = 0; p < 4; ++p) {
                uint32_t bh[4], bl[4];
                LDSM_X4(bh[0], bh[1], bh[2], bh[3],
                        bHi + p * 16 * GH_STRIDE + ko);
                LDSM_X4(bl[0], bl[1], bl[2], bl[3],
                        bLo + p * 16 * GH_STRIDE + ko);
                MMA16816(acc[0][p * 2 + 0], a0h, bh[0], bh[1]);
                MMA16816(acc[0][p * 2 + 1], a0h, bh[2], bh[3]);
                MMA16816(acc[1][p * 2 + 0], a1h, bh[0], bh[1]);
                MMA16816(acc[1][p * 2 + 1], a1h, bh[2], bh[3]);
                MMA16816(acc[0][p * 2 + 0], a0h, bl[0], bl[1]);
                MMA16816(acc[0][p * 2 + 1], a0h, bl[2], bl[3]);
                MMA16816(acc[1][p * 2 + 0], a1h, bl[0], bl[1]);
                MMA16816(acc[1][p * 2 + 1], a1h, bl[2], bl[3]);
                MMA16816(acc[0][p * 2 + 0], a0l, bh[0], bh[1]);
                MMA16816(acc[0][p * 2 + 1], a0l, bh[2], bh[3]);
                MMA16816(acc[1][p * 2 + 0], a1l, bh[0], bh[1]);
                MMA16816(acc[1][p * 2 + 1], a1l, bh[2], bh[3]);
            }
        }
        __syncthreads();
    }

    const int r  = lane >> 2;
    const int c2 = (lane & 3) * 2;
    #pragma unroll
    for (int f = 0; f < 2; ++f) {
        #pragma unroll
        for (int n8 = 0; n8 < 8; ++n8) {
            int n = n0 + wn + n8 * 8 + c2;
            float2 bv = *(const float2*)&bias[n];
            int m = m0 + wm + f * 16 + r;
            float2 r0; r0.x = acc[f][n8][0] + bv.x; r0.y = acc[f][n8][1] + bv.y;
            float2 r1; r1.x = acc[f][n8][2] + bv.x; r1.y = acc[f][n8][3] + bv.y;
            *(float2*)&out[(size_t)m * Hd + n] = r0;
            *(float2*)&out[(size_t)(m + 8) * Hd + n] = r1;
        }
    }
}

// =============================================================================
// Recurrence v9: R13 structure, but the 48 smem-resident weights per thread
// are stored as bf16 (hi only) — 96B instead of 192B -> smem weight
// wavefronts halved (768 -> 384). Unpack is 1 ALU op per weight:
// a bf16 in the TOP 16 bits of a u32 IS that fp32 value.
// 80 register-resident weights remain full fp32.
// =============================================================================
#define RREG 20   // float4 in registers (80 fp32)
#define RSMB 6    // uint4 of packed bf16 in smem (6*8 = 48 weights)
#define HSTR 132
#define HBUF (2 * 2 * HSTR)
#define REC_SMEM (HBUF * 4 + RSMB * 512 * 16)

__device__ __forceinline__ float fast_tanh(float x) {
    float e = __expf(2.0f * x);
    return 1.0f - 2.0f * __fdividef(1.0f, e + 1.0f);
}

__device__ __forceinline__ uint32_t pack_bf16x2(float a, float b) {
    __nv_bfloat162 h = __floats2bfloat162_rn(a, b);   // a -> low16, b -> high16
    uint32_t u; memcpy(&u, &h, 4); return u;
}

template<bool WRITE_H, bool FINAL>
__global__ void __launch_bounds__(512, 1) recur_kernel(
    const float* __restrict__ pre, const float* __restrict__ Whh,
    __nv_bfloat16* __restrict__ houthi, __nv_bfloat16* __restrict__ houtlo,
    const float* __restrict__ fcw, const float* __restrict__ fcb,
    float* __restrict__ out)
{
    extern __shared__ float smf[];
    float* hbuf = smf;                                // [2][2*HSTR]
    uint4* Wsm = (uint4*)(smf + HBUF);                // [RSMB][512]

    const int t  = threadIdx.x;
    const int b  = blockIdx.x;
    const int j  = t >> 1;
    const int kh = t & 1;

    const ulonglong2* wg =
        (const ulonglong2*)(Whh + (size_t)j * Hd + (kh << 7));
    ulonglong2 wr[RREG];
    #pragma unroll
    for (int c = 0; c < RREG; ++c) wr[c] = wg[c];

    // pack weights RREG..RREG+11 (48 fp32) into 6 uint4 of bf16 pairs
    #pragma unroll
    for (int c = 0; c < RSMB; ++c) {
        ulonglong2 wA = wg[RREG + 2 * c];
        ulonglong2 wB = wg[RREG + 2 * c + 1];
        float2 f0 = unpk(wA.x), f1 = unpk(wA.y);
        float2 f2 = unpk(wB.x), f3 = unpk(wB.y);
        Wsm[c * 512 + t] = make_uint4(
            pack_bf16x2(f0.x, f0.y), pack_bf16x2(f1.x, f1.y),
            pack_bf16x2(f2.x, f2.y), pack_bf16x2(f3.x, f3.y));
    }

    if (t < HBUF) hbuf[t] = 0.f;

    const float* preb = pre + (size_t)b * Tlen * Hd;
    float p = preb[j];
    const int wslot = j + ((j >> 7) << 2);
    __syncthreads();

    for (int step = 0; step < Tlen; ++step) {
        int sn = (step + 1 < Tlen) ? step + 1 : step;
        float pn = preb[sn * Hd + j];

        const ulonglong2* h2 =
            (const ulonglong2*)(hbuf + (step & 1) * (2 * HSTR) + kh * HSTR);

        u64 a0 = 0ull, a1 = 0ull, a2 = 0ull, a3 = 0ull, a4 = 0ull, a5 = 0ull;

        // bf16-packed smem weights first (fills LSU early)
        #pragma unroll
        for (int c = 0; c < RSMB; ++c) {
            uint4 wv = Wsm[c * 512 + t];
            ulonglong2 hvA = h2[RREG + 2 * c];
            ulonglong2 hvB = h2[RREG + 2 * c + 1];
            fma2(a4, mk64(wv.x << 16, wv.x & 0xFFFF0000u), hvA.x);
            fma2(a5, mk64(wv.y << 16, wv.y & 0xFFFF0000u), hvA.y);
            fma2(a4, mk64(wv.z << 16, wv.z & 0xFFFF0000u), hvB.x);
            fma2(a5, mk64(wv.w << 16, wv.w & 0xFFFF0000u), hvB.y);
        }
        #pragma unroll
        for (int c = 0; c < RREG; c += 2) {
            ulonglong2 hv = h2[c];
            fma2(a0, wr[c].x, hv.x);
            fma2(a1, wr[c].y, hv.y);
            ulonglong2 hw = h2[c + 1];
            fma2(a2, wr[c + 1].x, hw.x);
            fma2(a3, wr[c + 1].y, hw.y);
        }

        u64 s01 = add2(add2(add2(a0, a1), add2(a2, a3)), add2(a4, a5));
        float2 f = unpk(s01);
        float d = f.x + f.y;
        d += __shfl_xor_sync(0xffffffffu, d, 1);

        float hn = fast_tanh(p + d);

        if (kh == 0) {
            hbuf[((step + 1) & 1) * (2 * HSTR) + wslot] = hn;
            if (WRITE_H) {
                __nv_bfloat16 hh = __float2bfloat16_rn(hn);
                float rem = hn - __bfloat162float(hh);
                size_t o = ((size_t)b * Tlen + step) * Hd + j;
                houthi[o] = hh;
                houtlo[o] = __float2bfloat16_rn(rem);
            }
        }
        __syncthreads();
        p = pn;
    }

    if (FINAL) {
        if (t < 64) {
            int o = t >> 5, lane = t & 31;
            float s = 0.f;
            #pragma unroll
            for (int q = 0; q < 8; ++q) {
                int jj = lane + (q << 5);
                s += hbuf[jj + ((jj >> 7) << 2)] * fcw[o * Hd + jj];
            }
            #pragma unroll
            for (int off = 16; off; off >>= 1)
                s += __shfl_down_sync(0xffffffffu, s, off);
            if (lane == 0) out[b * NOUT + o] = s + fcb[o];
        }
    }
}

extern "C" void kernel_launch(void* const* d_in, const int* in_sizes, int n_in,
                              void* d_out, int out_size) {
    const float* x    = (const float*)d_in[0];
    const float* Wxh0 = (const float*)d_in[1];
    const float* Whh0 = (const float*)d_in[2];
    const float* b0   = (const float*)d_in[3];
    const float* Wxh1 = (const float*)d_in[4];
    const float* Whh1 = (const float*)d_in[5];
    const float* b1   = (const float*)d_in[6];
    const float* fcw  = (const float*)d_in[7];
    const float* fcb  = (const float*)d_in[8];
    float* out = (float*)d_out;

    float* bufA = nullptr;
    __nv_bfloat16 *xhi, *xlo, *h1hi, *h1lo, *w0hi, *w0lo, *w1hi, *w1lo;
    cudaGetSymbolAddress((void**)&bufA, g_bufA);
    cudaGetSymbolAddress((void**)&xhi, g_xhi);
    cudaGetSymbolAddress((void**)&xlo, g_xlo);
    cudaGetSymbolAddress((void**)&h1hi, g_h1hi);
    cudaGetSymbolAddress((void**)&h1lo, g_h1lo);
    cudaGetSymbolAddress((void**)&w0hi, g_w0hi);
    cudaGetSymbolAddress((void**)&w0lo, g_w0lo);
    cudaGetSymbolAddress((void**)&w1hi, g_w1hi);
    cudaGetSymbolAddress((void**)&w1lo, g_w1lo);

    cudaFuncSetAttribute(gemm_hmma_kernel,
        cudaFuncAttributeMaxDynamicSharedMemorySize, GH_SMEM);
    cudaFuncSetAttribute(recur_kernel<true, false>,
        cudaFuncAttributeMaxDynamicSharedMemorySize, REC_SMEM);
    cudaFuncSetAttribute(recur_kernel<false, true>,
        cudaFuncAttributeMaxDynamicSharedMemorySize, REC_SMEM);

    const int NX4 = (Bsz * Tlen * Hd) / 4;
    const int NW4 = (Hd * Hd) / 4;

    conv_hilo_kernel<<<NX4 / 256, 256>>>(x, xhi, xlo, NX4);
    conv_hilo_kernel<<<NW4 / 256, 256>>>(Wxh0, w0hi, w0lo, NW4);
    conv_hilo_kernel<<<NW4 / 256, 256>>>(Wxh1, w1hi, w1lo, NW4);

    // Layer 1
    gemm_hmma_kernel<<<2048, 256, GH_SMEM>>>(xhi, xlo, w0hi, w0lo, b0, bufA);
    recur_kernel<true, false><<<Bsz, 512, REC_SMEM>>>(
        bufA, Whh0, h1hi, h1lo, nullptr, nullptr, nullptr);

    // Layer 2 + head
    gemm_hmma_kernel<<<2048, 256, GH_SMEM>>>(h1hi, h1lo, w1hi, w1lo, b1, bufA);
    recur_kernel<false, true><<<Bsz, 512, REC_SMEM>>>(
        bufA, Whh1, nullptr, nullptr, fcw, fcb, out);
}